// round 4
// baseline (speedup 1.0000x reference)
#include <cuda_runtime.h>

#define NB 4
#define NC 19
#define NH 192
#define NW 192
#define HW (NH*NW)
#define THETA 40.0f
#define PAD 193
#define SMEM_BYTES (NH*PAD*4)

// Scratch (device globals: no runtime allocation allowed)
__device__ float g_colagg[NB*NC*HW];   // per-(b,c) column aggregation scratch
__device__ float g_D   [NB*HW];        // D[b][i][j]  = exp(-theta * relu(edge))
__device__ float g_Dt  [NB*HW];        // Dt[b][j][i] = D[b][i][j]
__device__ float g_Zc  [NB*HW];        // column ones-scan result
__device__ float g_ST  [NB*HW];        // row ones-scan forward scratch (transposed)
__device__ float g_Zinv[NB*HW];        // 1/Z

// ---------------------------------------------------------------------------
// PK1: per (b,j) column: compute decays D, Dt, and column ones-scan Zc.
// ---------------------------------------------------------------------------
__global__ void pk1_kernel(const float* __restrict__ edge) {
    int t = blockIdx.x * blockDim.x + threadIdx.x;   // 0 .. NB*NW-1
    if (t >= NB*NW) return;
    int b = t / NW;
    int j = t - b*NW;
    const float* eb = edge + b*HW + j;     // stride NW over i
    float* Db  = g_D  + b*HW + j;
    float* Zb  = g_Zc + b*HW + j;
    float* Dtb = g_Dt + b*HW + j*NW;       // Dt[b][j][i], stride 1 over i

    float S = 0.f;
    #pragma unroll 4
    for (int i = 0; i < NH; ++i) {
        float e = fmaxf(eb[i*NW], 0.f);
        float d = __expf(-THETA * e);
        Db[i*NW] = d;
        Dtb[i]   = d;
        S = d * S + 1.f;
        Zb[i*NW] = S;
    }
    float T = 0.f, c = 0.f;
    #pragma unroll 4
    for (int i = NH-1; i >= 0; --i) {
        T = 1.f + c * T;
        Zb[i*NW] += T - 1.f;               // Zc = S + T - 1
        c = Db[i*NW];
    }
}

// ---------------------------------------------------------------------------
// PK2: per (b,i) row: row ones-scan; Zinv = 1/(Zc + Zr), Zr = Sr + Tr - 2.
// ---------------------------------------------------------------------------
__global__ void pk2_kernel() {
    int t = blockIdx.x * blockDim.x + threadIdx.x;   // 0 .. NB*NH-1
    if (t >= NB*NH) return;
    int b = t / NH;
    int i = t - b*NH;
    const float* Dti = g_Dt + b*HW + i;    // stride NW over j (coalesced over threads)
    float* STb = g_ST + b*HW + i;
    const float* Zcb = g_Zc   + b*HW + i*NW;
    float* Zib       = g_Zinv + b*HW + i*NW;

    float S = 0.f;
    #pragma unroll 4
    for (int j = 0; j < NW; ++j) {
        S = Dti[j*NW] * S + 1.f;
        STb[j*NW] = S;
    }
    float T = 0.f, c = 0.f;
    #pragma unroll 4
    for (int j = NW-1; j >= 0; --j) {
        T = 1.f + c * T;
        float Zr = STb[j*NW] + T - 2.f;    // exclude s==j
        Zib[j] = 1.f / (Zcb[j] + Zr);
        c = Dti[j*NW];
    }
}

// ---------------------------------------------------------------------------
// Iteration kernel: one CTA per (b,c) slice, slice in smem A[192][193].
// SIMPLE loops only (R3 lesson: register arrays + full unroll => 255 regs,
// local-memory spills inside the serial scan chains => 16x slowdown).
//   Phase A: col scans (thread per column j): fwd S -> g_colagg, bwd RMW adds T.
//   Phase B: row scans in-place in smem (thread per row i), f recovered from S.
//   Phase C: out = (colagg + rowagg) * Zinv.
// In-place fin==fout safe: slice fully read before phase C writes.
// ---------------------------------------------------------------------------
__global__ void __launch_bounds__(256, 1)
iter_kernel(const float* __restrict__ fin, float* __restrict__ fout) {
    extern __shared__ float A[];           // [NH][PAD]
    int bc = blockIdx.x;
    int b  = bc / NC;
    int base  = bc * HW;
    int dbase = b  * HW;
    int tid = threadIdx.x;

    // load slice, vectorized (HW % 4 == 0, NW % 4 == 0)
    {
        const float4* f4 = (const float4*)(fin + base);
        for (int v = tid; v < HW/4; v += 256) {
            int idx = v * 4;
            int i = idx / NW;
            int j = idx - i*NW;
            float4 x = f4[v];
            float* Ap = A + i*PAD + j;
            Ap[0] = x.x; Ap[1] = x.y; Ap[2] = x.z; Ap[3] = x.w;
        }
    }
    __syncthreads();

    // Phase A: column scans, thread per column j
    if (tid < NW) {
        int j = tid;
        const float* Dj = g_D + dbase + j;       // coalesced over threads, L2/L1-hot
        float* cg = g_colagg + base + j;
        float S = 0.f;
        #pragma unroll 4
        for (int i = 0; i < NH; ++i) {
            S = Dj[i*NW] * S + A[i*PAD + j];
            cg[i*NW] = S;
        }
        float T = 0.f, c = 0.f;
        #pragma unroll 4
        for (int i = NH-1; i >= 0; --i) {
            float f = A[i*PAD + j];
            T = f + c * T;                       // T_{H-1} = f
            cg[i*NW] += T - f;                   // colagg = S + T - f
            c = Dj[i*NW];
        }
    }
    __syncthreads();

    // Phase B: row scans in-place, thread per row i
    if (tid < NH) {
        int i = tid;
        const float* Dti = g_Dt + dbase + i;     // stride NW over j, coalesced over threads
        float* Ai = A + i*PAD;
        float S = 0.f;
        #pragma unroll 4
        for (int j = 0; j < NW; ++j) {
            S = Dti[j*NW] * S + Ai[j];
            Ai[j] = S;                           // A now holds S_j
        }
        float T = 0.f, c = 0.f;
        #pragma unroll 4
        for (int j = NW-1; j >= 0; --j) {
            float Sj = Ai[j];
            float dj = (j > 0) ? Dti[j*NW] : 0.f;
            float f  = (j > 0) ? (Sj - dj * Ai[j-1]) : Sj;   // recover f from S
            T = f + c * T;                       // T_{W-1} = f
            Ai[j] = Sj + T - 2.f*f;              // rowagg (excludes s==j)
            c = dj;
        }
    }
    __syncthreads();

    // Phase C: combine, vectorized
    {
        const float4* Zi4 = (const float4*)(g_Zinv + dbase);
        const float4* cg4 = (const float4*)(g_colagg + base);
        float4* out4      = (float4*)(fout + base);
        for (int v = tid; v < HW/4; v += 256) {
            int idx = v * 4;
            int i = idx / NW;
            int j = idx - i*NW;
            float4 cgv = cg4[v];
            float4 zv  = Zi4[v];
            const float* Ap = A + i*PAD + j;
            float4 o;
            o.x = (cgv.x + Ap[0]) * zv.x;
            o.y = (cgv.y + Ap[1]) * zv.y;
            o.z = (cgv.z + Ap[2]) * zv.z;
            o.w = (cgv.w + Ap[3]) * zv.w;
            out4[v] = o;
        }
    }
}

// ---------------------------------------------------------------------------
extern "C" void kernel_launch(void* const* d_in, const int* in_sizes, int n_in,
                              void* d_out, int out_size) {
    const float* mask = (const float*)d_in[0];   // (4,19,192,192) fp32
    const float* edge = (const float*)d_in[1];   // (4,1,192,192)  fp32
    float* out = (float*)d_out;

    cudaFuncSetAttribute(iter_kernel,
                         cudaFuncAttributeMaxDynamicSharedMemorySize, SMEM_BYTES);

    pk1_kernel<<<24, 32>>>(edge);
    pk2_kernel<<<24, 32>>>();

    iter_kernel<<<NB*NC, 256, SMEM_BYTES>>>(mask, out);  // iter 1
    iter_kernel<<<NB*NC, 256, SMEM_BYTES>>>(out,  out);  // iter 2 (in-place safe)
    iter_kernel<<<NB*NC, 256, SMEM_BYTES>>>(out,  out);  // iter 3
}

// round 10
// speedup vs baseline: 1.6485x; 1.6485x over previous
#include <cuda_runtime.h>
#include <cstdint>

#define NB 4
#define NC 19
#define NH 192
#define NW 192
#define HW (NH*NW)
#define THETA 40.0f
#define PAD 193
#define BLK 32
#define NBLK 6
#define STG (BLK*NW)                 // 6144 floats = 24 KB per stage buffer
#define SMEM_BYTES ((NH*PAD + 2*STG)*4)

// Scratch (device globals: no runtime allocation allowed)
__device__ float g_colagg[NB*NC*HW];
__device__ float g_D   [NB*HW];      // D[b][i][j]
__device__ float g_Dt  [NB*HW];      // Dt[b][j][i]
__device__ float g_Zc  [NB*HW];
__device__ float g_ST  [NB*HW];
__device__ float g_Zinv[NB*HW];

// ---------------------------------------------------------------------------
__device__ __forceinline__ void stage_async(float* sdst, const float* gsrc, int tid) {
    unsigned int s = (unsigned int)__cvta_generic_to_shared(sdst);
    #pragma unroll
    for (int r = 0; r < STG/4/256; ++r) {          // 6 x 16B per thread
        int v = tid + r*256;
        asm volatile("cp.async.cg.shared.global [%0], [%1], 16;\n"
                     :: "r"(s + v*16), "l"(gsrc + v*4));
    }
    asm volatile("cp.async.commit_group;\n");
}
__device__ __forceinline__ void cp_wait(bool more) {
    if (more) asm volatile("cp.async.wait_group 1;\n");
    else      asm volatile("cp.async.wait_group 0;\n");
}

// ---------------------------------------------------------------------------
// PK0: elementwise decays, massively parallel
__global__ void pk0_kernel(const float* __restrict__ edge) {
    int t = blockIdx.x * blockDim.x + threadIdx.x;
    if (t >= NB*HW) return;
    int b = t / HW;
    int r = t - b*HW;
    int i = r / NW;
    int j = r - i*NW;
    float d = __expf(-THETA * fmaxf(edge[t], 0.f));
    g_D [t] = d;
    g_Dt[b*HW + j*NW + i] = d;
}

// PK1: per (b,j) column ones-scan Zc (reads L2-hot g_D)
__global__ void pk1_kernel() {
    int t = blockIdx.x * blockDim.x + threadIdx.x;
    if (t >= NB*NW) return;
    int b = t / NW;
    int j = t - b*NW;
    const float* Db = g_D  + b*HW + j;
    float* Zb       = g_Zc + b*HW + j;
    float S = 0.f;
    #pragma unroll 8
    for (int i = 0; i < NH; ++i) {
        S = Db[i*NW] * S + 1.f;
        Zb[i*NW] = S;
    }
    float T = 0.f, c = 0.f;
    #pragma unroll 8
    for (int i = NH-1; i >= 0; --i) {
        T = 1.f + c * T;
        Zb[i*NW] += T - 1.f;               // Zc = S + T - 1
        c = Db[i*NW];
    }
}

// PK2: per (b,i) row ones-scan; Zinv = 1/(Zc + Zr), Zr = Sr + Tr - 2
__global__ void pk2_kernel() {
    int t = blockIdx.x * blockDim.x + threadIdx.x;
    if (t >= NB*NH) return;
    int b = t / NH;
    int i = t - b*NH;
    const float* Dti = g_Dt + b*HW + i;
    float* STb = g_ST + b*HW + i;
    const float* Zcb = g_Zc   + b*HW + i*NW;
    float* Zib       = g_Zinv + b*HW + i*NW;
    float S = 0.f;
    #pragma unroll 8
    for (int j = 0; j < NW; ++j) {
        S = Dti[j*NW] * S + 1.f;
        STb[j*NW] = S;
    }
    float T = 0.f, c = 0.f;
    #pragma unroll 8
    for (int j = NW-1; j >= 0; --j) {
        T = 1.f + c * T;
        float Zr = STb[j*NW] + T - 2.f;
        Zib[j] = 1.f / (Zcb[j] + Zr);
        c = Dti[j*NW];
    }
}

// ---------------------------------------------------------------------------
// Iteration kernel: CTA per (b,c). Feat slice in smem A[192][193]; decays
// streamed block-by-block (32 rows) into double-buffered smem via cp.async so
// the serial scan chains never wait on global memory (R4 lesson: exposed
// per-step L2 latency was the whole 171us).
// ---------------------------------------------------------------------------
__global__ void __launch_bounds__(256, 1)
iter_kernel(const float* __restrict__ fin, float* __restrict__ fout) {
    extern __shared__ float smem[];
    float* A   = smem;                   // [NH][PAD]
    float* Ds0 = smem + NH*PAD;          // [BLK][NW]
    float* Ds1 = Ds0 + STG;

    int bc = blockIdx.x;
    int b  = bc / NC;
    int base  = bc * HW;
    int dbase = b  * HW;
    int tid = threadIdx.x;

    const float* Dsrc  = g_D  + dbase;
    const float* DtSrc = g_Dt + dbase;
    float* cg = g_colagg + base;

    // load feat slice (coalesced float4)
    {
        const float4* f4 = (const float4*)(fin + base);
        #pragma unroll
        for (int r = 0; r < HW/4/256; ++r) {
            int v = tid + r*256;
            int idx = v * 4;
            int i = idx / NW;
            int j = idx - i*NW;
            float4 x = f4[v];
            float* Ap = A + i*PAD + j;
            Ap[0] = x.x; Ap[1] = x.y; Ap[2] = x.z; Ap[3] = x.w;
        }
    }
    __syncthreads();

    // ---- Phase A forward: col scans (thread = column j), S -> cg ----
    {
        stage_async(Ds0, Dsrc, tid);
        float S = 0.f;
        for (int blk = 0; blk < NBLK; ++blk) {
            float* buf = (blk & 1) ? Ds1 : Ds0;
            bool more = (blk + 1 < NBLK);
            if (more) stage_async((blk & 1) ? Ds0 : Ds1, Dsrc + (blk+1)*STG, tid);
            cp_wait(more);
            __syncthreads();
            if (tid < NW) {
                int i0 = blk*BLK;
                #pragma unroll
                for (int k = 0; k < BLK; ++k) {
                    S = buf[k*NW + tid] * S + A[(i0+k)*PAD + tid];
                    cg[(i0+k)*NW + tid] = S;
                }
            }
            __syncthreads();
        }
    }

    // ---- Phase A backward: cg <- S + T - f ----
    // Block NBLK-1's decay tile is still resident in Ds1 from forward's last
    // iteration — skip its re-stage and start the pipeline one block deeper.
    {
        float T = 0.f, c = 0.f;
        for (int blk = NBLK-1; blk >= 0; --blk) {
            float* buf = (blk & 1) ? Ds1 : Ds0;
            bool more = (blk - 1 >= 0);
            if (more) stage_async((blk & 1) ? Ds0 : Ds1, Dsrc + (blk-1)*STG, tid);
            cp_wait(more);
            __syncthreads();
            if (tid < NW) {
                int i0 = blk*BLK;
                #pragma unroll
                for (int k = BLK-1; k >= 0; --k) {
                    float f = A[(i0+k)*PAD + tid];
                    float prev = cg[(i0+k)*NW + tid];
                    T = f + c * T;
                    cg[(i0+k)*NW + tid] = prev + T - f;
                    c = buf[k*NW + tid];
                }
            }
            __syncthreads();
        }
    }

    // ---- Phase B forward: row scans in-place (thread = row i), A <- S ----
    {
        stage_async(Ds0, DtSrc, tid);
        float S = 0.f;
        for (int blk = 0; blk < NBLK; ++blk) {
            float* buf = (blk & 1) ? Ds1 : Ds0;
            bool more = (blk + 1 < NBLK);
            if (more) stage_async((blk & 1) ? Ds0 : Ds1, DtSrc + (blk+1)*STG, tid);
            cp_wait(more);
            __syncthreads();
            if (tid < NH) {
                int j0 = blk*BLK;
                float* Ai = A + tid*PAD;
                #pragma unroll
                for (int k = 0; k < BLK; ++k) {
                    S = buf[k*NW + tid] * S + Ai[j0+k];
                    Ai[j0+k] = S;
                }
            }
            __syncthreads();
        }
    }

    // ---- Phase B backward: A <- rowagg = S + T - 2f (f recovered from S) ----
    // Block NBLK-1's Dt tile still resident in Ds1 — skip re-stage.
    {
        float T = 0.f, c = 0.f;
        for (int blk = NBLK-1; blk >= 0; --blk) {
            float* buf = (blk & 1) ? Ds1 : Ds0;
            bool more = (blk - 1 >= 0);
            if (more) stage_async((blk & 1) ? Ds0 : Ds1, DtSrc + (blk-1)*STG, tid);
            cp_wait(more);
            __syncthreads();
            if (tid < NH) {
                int j0 = blk*BLK;
                float* Ai = A + tid*PAD;
                #pragma unroll
                for (int k = BLK-1; k >= 0; --k) {
                    int j = j0 + k;
                    float Sj = Ai[j];
                    float dj = (j > 0) ? buf[k*NW + tid] : 0.f;
                    float f  = (j > 0) ? (Sj - dj * Ai[j-1]) : Sj;
                    T = f + c * T;
                    Ai[j] = Sj + T - 2.f*f;
                    c = dj;
                }
            }
            __syncthreads();
        }
    }

    // ---- Phase C: combine (coalesced float4) ----
    {
        const float4* Zi4 = (const float4*)(g_Zinv + dbase);
        const float4* cg4 = (const float4*)(g_colagg + base);
        float4* out4      = (float4*)(fout + base);
        #pragma unroll
        for (int r = 0; r < HW/4/256; ++r) {
            int v = tid + r*256;
            int idx = v * 4;
            int i = idx / NW;
            int j = idx - i*NW;
            float4 cgv = cg4[v];
            float4 zv  = Zi4[v];
            const float* Ap = A + i*PAD + j;
            float4 o;
            o.x = (cgv.x + Ap[0]) * zv.x;
            o.y = (cgv.y + Ap[1]) * zv.y;
            o.z = (cgv.z + Ap[2]) * zv.z;
            o.w = (cgv.w + Ap[3]) * zv.w;
            out4[v] = o;
        }
    }
}

// ---------------------------------------------------------------------------
extern "C" void kernel_launch(void* const* d_in, const int* in_sizes, int n_in,
                              void* d_out, int out_size) {
    const float* mask = (const float*)d_in[0];   // (4,19,192,192) fp32
    const float* edge = (const float*)d_in[1];   // (4,1,192,192)  fp32
    float* out = (float*)d_out;

    cudaFuncSetAttribute(iter_kernel,
                         cudaFuncAttributeMaxDynamicSharedMemorySize, SMEM_BYTES);

    pk0_kernel<<<(NB*HW + 255)/256, 256>>>(edge);
    pk1_kernel<<<6, 128>>>();
    pk2_kernel<<<6, 128>>>();

    iter_kernel<<<NB*NC, 256, SMEM_BYTES>>>(mask, out);  // iter 1
    iter_kernel<<<NB*NC, 256, SMEM_BYTES>>>(out,  out);  // iter 2 (in-place safe)
    iter_kernel<<<NB*NC, 256, SMEM_BYTES>>>(out,  out);  // iter 3
}

// round 15
// speedup vs baseline: 4.8727x; 2.9558x over previous
#include <cuda_runtime.h>
#include <cstdint>

#define NB 4
#define NC 19
#define NH 192
#define NW 192
#define HW (NH*NW)
#define THETA 40.0f
#define PAD 193
#define BLK 32
#define NBLK 6
#define STG (BLK*NW)                 // 6144 floats = 24 KB per stage buffer
#define SMEM_BYTES ((NH*PAD + 2*STG)*4)

__device__ float g_colagg[NB*NC*HW];
__device__ float g_D   [NB*HW];      // D[b][i][j]
__device__ float g_Dt  [NB*HW];      // Dt[b][j][i]
__device__ float g_Zc  [NB*HW];
__device__ float g_Zinv[NB*HW];

// ---------------------------------------------------------------------------
__device__ __forceinline__ void stage_async(float* sdst, const float* gsrc, int tid) {
    unsigned int s = (unsigned int)__cvta_generic_to_shared(sdst);
    #pragma unroll
    for (int r = 0; r < STG/4/256; ++r) {
        int v = tid + r*256;
        asm volatile("cp.async.cg.shared.global [%0], [%1], 16;\n"
                     :: "r"(s + v*16), "l"(gsrc + v*4));
    }
    asm volatile("cp.async.commit_group;\n");
}
__device__ __forceinline__ void cp_wait(bool more) {
    if (more) asm volatile("cp.async.wait_group 1;\n");
    else      asm volatile("cp.async.wait_group 0;\n");
}

// ---------------------------------------------------------------------------
// PK0: decays + tiled transpose (both D and Dt written coalesced)
__global__ void pk0_kernel(const float* __restrict__ edge) {
    __shared__ float t[32][33];
    int b  = blockIdx.z;
    int i0 = blockIdx.y * 32;
    int j0 = blockIdx.x * 32;
    int tx = threadIdx.x, ty = threadIdx.y;
    #pragma unroll
    for (int r = ty; r < 32; r += 8) {
        float e = edge[b*HW + (i0+r)*NW + j0 + tx];
        float d = __expf(-THETA * fmaxf(e, 0.f));
        g_D[b*HW + (i0+r)*NW + j0 + tx] = d;
        t[r][tx] = d;
    }
    __syncthreads();
    #pragma unroll
    for (int r = ty; r < 32; r += 8) {
        g_Dt[b*HW + (j0+r)*NW + i0 + tx] = t[tx][r];
    }
}

// ---------------------------------------------------------------------------
// Warp affine-scan: one warp per line, 6 elems/lane, shfl scan of (a,b) pairs.
// S_i = d_i * S_{i-1} + 1 over 192 elements.
// ---------------------------------------------------------------------------
// pkZc: one warp per (b, j) column line. Decays = row j of Dt (coalesced).
// Writes Zc[b][i][j] = S_i + T_i - 1 (scatter, stride NW).
__global__ void pkZc_kernel() {
    int gw = (blockIdx.x * blockDim.x + threadIdx.x) >> 5;
    if (gw >= NB*NW) return;
    int lane = threadIdx.x & 31;
    int b = gw / NW, j = gw - b*NW;
    const float* dt = g_Dt + b*HW + j*NW;     // d_i contiguous in i

    float dd[6];
    #pragma unroll
    for (int e = 0; e < 6; ++e) dd[e] = dt[lane*6 + e];

    float a = 1.f, s = 0.f;
    #pragma unroll
    for (int e = 0; e < 6; ++e) { s = dd[e]*s + 1.f; a *= dd[e]; }
    #pragma unroll
    for (int off = 1; off < 32; off <<= 1) {
        float pa = __shfl_up_sync(0xffffffffu, a, off);
        float pb = __shfl_up_sync(0xffffffffu, s, off);
        if (lane >= off) { s = a*pb + s; a = a*pa; }
    }
    float pre = __shfl_up_sync(0xffffffffu, s, 1);
    if (lane == 0) pre = 0.f;
    float Sv[6]; float x = pre;
    #pragma unroll
    for (int e = 0; e < 6; ++e) { x = dd[e]*x + 1.f; Sv[e] = x; }

    // backward: T'_r = c'_r * T'_{r-1} + 1, c'_r = d[192-r], c'_0 = 0
    float cc[6];
    #pragma unroll
    for (int e = 0; e < 6; ++e) {
        int r = lane*6 + e;
        cc[e] = (r == 0) ? 0.f : dt[192 - r];
    }
    float ab = 1.f, sb = 0.f;
    #pragma unroll
    for (int e = 0; e < 6; ++e) { sb = cc[e]*sb + 1.f; ab *= cc[e]; }
    #pragma unroll
    for (int off = 1; off < 32; off <<= 1) {
        float pa = __shfl_up_sync(0xffffffffu, ab, off);
        float pb = __shfl_up_sync(0xffffffffu, sb, off);
        if (lane >= off) { sb = ab*pb + sb; ab = ab*pa; }
    }
    float preb = __shfl_up_sync(0xffffffffu, sb, 1);
    if (lane == 0) preb = 0.f;
    float Tv[6]; x = preb;
    #pragma unroll
    for (int e = 0; e < 6; ++e) { x = cc[e]*x + 1.f; Tv[e] = x; }

    // T at i = 6*lane+e lives at lane 31-lane, element 5-e
    float* zc = g_Zc + b*HW + j;
    #pragma unroll
    for (int e = 0; e < 6; ++e) {
        float Ti = __shfl_sync(0xffffffffu, Tv[5-e], 31 - lane);
        zc[(lane*6 + e)*NW] = Sv[e] + Ti - 1.f;
    }
}

// pkZr: one warp per (b, i) row line. Decays = row i of D (coalesced).
// Zr = S + T - 2; writes Zinv = 1/(Zc + Zr) (coalesced).
__global__ void pkZr_kernel() {
    int gw = (blockIdx.x * blockDim.x + threadIdx.x) >> 5;
    if (gw >= NB*NH) return;
    int lane = threadIdx.x & 31;
    int b = gw / NH, i = gw - b*NH;
    const float* dr = g_D + b*HW + i*NW;

    float dd[6];
    #pragma unroll
    for (int e = 0; e < 6; ++e) dd[e] = dr[lane*6 + e];

    float a = 1.f, s = 0.f;
    #pragma unroll
    for (int e = 0; e < 6; ++e) { s = dd[e]*s + 1.f; a *= dd[e]; }
    #pragma unroll
    for (int off = 1; off < 32; off <<= 1) {
        float pa = __shfl_up_sync(0xffffffffu, a, off);
        float pb = __shfl_up_sync(0xffffffffu, s, off);
        if (lane >= off) { s = a*pb + s; a = a*pa; }
    }
    float pre = __shfl_up_sync(0xffffffffu, s, 1);
    if (lane == 0) pre = 0.f;
    float Sv[6]; float x = pre;
    #pragma unroll
    for (int e = 0; e < 6; ++e) { x = dd[e]*x + 1.f; Sv[e] = x; }

    float cc[6];
    #pragma unroll
    for (int e = 0; e < 6; ++e) {
        int r = lane*6 + e;
        cc[e] = (r == 0) ? 0.f : dr[192 - r];
    }
    float ab = 1.f, sb = 0.f;
    #pragma unroll
    for (int e = 0; e < 6; ++e) { sb = cc[e]*sb + 1.f; ab *= cc[e]; }
    #pragma unroll
    for (int off = 1; off < 32; off <<= 1) {
        float pa = __shfl_up_sync(0xffffffffu, ab, off);
        float pb = __shfl_up_sync(0xffffffffu, sb, off);
        if (lane >= off) { sb = ab*pb + sb; ab = ab*pa; }
    }
    float preb = __shfl_up_sync(0xffffffffu, sb, 1);
    if (lane == 0) preb = 0.f;
    float Tv[6]; x = preb;
    #pragma unroll
    for (int e = 0; e < 6; ++e) { x = cc[e]*x + 1.f; Tv[e] = x; }

    const float* zc = g_Zc  + b*HW + i*NW;
    float*      zi = g_Zinv + b*HW + i*NW;
    #pragma unroll
    for (int e = 0; e < 6; ++e) {
        float Ti = __shfl_sync(0xffffffffu, Tv[5-e], 31 - lane);
        int jj = lane*6 + e;
        float Zr = Sv[e] + Ti - 2.f;
        zi[jj] = 1.f / (zc[jj] + Zr);
    }
}

// ---------------------------------------------------------------------------
// Iteration kernel v3: CTA per (b,c). smem A[192][193] + double-buffered
// cp.async decay staging. Phase A forward is STORELESS (checkpoints only);
// backward recomputes S per block in registers and writes colagg ONCE.
// Phase B chains run on register-batched operands. Outer block loops are
// NOT unrolled (R3 lesson: outer unroll x register arrays => spills).
// ---------------------------------------------------------------------------
__global__ void __launch_bounds__(256, 1)
iter_kernel(const float* __restrict__ fin, float* __restrict__ fout) {
    extern __shared__ float smem[];
    float* A   = smem;                   // [NH][PAD]
    float* Ds0 = smem + NH*PAD;
    float* Ds1 = Ds0 + STG;

    int bc = blockIdx.x;
    int b  = bc / NC;
    int base  = bc * HW;
    int dbase = b  * HW;
    int tid = threadIdx.x;

    const float* Dsrc  = g_D  + dbase;
    const float* DtSrc = g_Dt + dbase;
    float* cg = g_colagg + base;

    // load feat slice
    {
        const float4* f4 = (const float4*)(fin + base);
        #pragma unroll
        for (int r = 0; r < HW/4/256; ++r) {
            int v = tid + r*256;
            int idx = v * 4;
            int i = idx / NW;
            int j = idx - i*NW;
            float4 x = f4[v];
            float* Ap = A + i*PAD + j;
            Ap[0] = x.x; Ap[1] = x.y; Ap[2] = x.z; Ap[3] = x.w;
        }
    }
    __syncthreads();

    float chk[NBLK];

    // ---- Phase A forward (storeless): col chains, checkpoints only ----
    {
        stage_async(Ds0, Dsrc, tid);
        float S = 0.f;
        for (int blk = 0; blk < NBLK; ++blk) {
            float* buf = (blk & 1) ? Ds1 : Ds0;
            bool more = (blk + 1 < NBLK);
            if (more) stage_async((blk & 1) ? Ds0 : Ds1, Dsrc + (blk+1)*STG, tid);
            cp_wait(more);
            __syncthreads();
            if (tid < NW) {
                int i0 = blk*BLK;
                #pragma unroll
                for (int k = 0; k < BLK; ++k)
                    S = buf[k*NW + tid] * S + A[(i0+k)*PAD + tid];
            }
            chk[blk] = S;
            __syncthreads();
        }
    }

    // ---- Phase A backward: recompute S per block, write colagg once ----
    // Block NBLK-1's D tile resident in Ds1.
    {
        float T = 0.f, c = 0.f;
        for (int blk = NBLK-1; blk >= 0; --blk) {
            float* buf = (blk & 1) ? Ds1 : Ds0;
            bool more = (blk > 0);
            if (more) stage_async((blk & 1) ? Ds0 : Ds1, Dsrc + (blk-1)*STG, tid);
            cp_wait(more);
            __syncthreads();
            if (tid < NW) {
                int i0 = blk*BLK;
                float sprev = (blk > 0) ? chk[blk-1] : 0.f;
                float dr[BLK], sr[BLK];
                float s = sprev;
                #pragma unroll
                for (int k = 0; k < BLK; ++k) {
                    dr[k] = buf[k*NW + tid];
                    s = dr[k]*s + A[(i0+k)*PAD + tid];
                    sr[k] = s;
                }
                #pragma unroll
                for (int k = BLK-1; k >= 0; --k) {
                    float sp = (k > 0) ? sr[k-1] : sprev;
                    float f  = sr[k] - dr[k]*sp;       // recover f
                    T = f + c*T;
                    cg[(i0+k)*NW + tid] = sr[k] + T - f;
                    c = dr[k];
                }
            }
            __syncthreads();
        }
    }

    // ---- Phase B forward: row chains, register-batched, A <- S ----
    {
        stage_async(Ds0, DtSrc, tid);
        float S = 0.f;
        for (int blk = 0; blk < NBLK; ++blk) {
            float* buf = (blk & 1) ? Ds1 : Ds0;
            bool more = (blk + 1 < NBLK);
            if (more) stage_async((blk & 1) ? Ds0 : Ds1, DtSrc + (blk+1)*STG, tid);
            cp_wait(more);
            __syncthreads();
            if (tid < NH) {
                int j0 = blk*BLK;
                float* Ai = A + tid*PAD;
                float dr[BLK], fr[BLK];
                #pragma unroll
                for (int k = 0; k < BLK; ++k) {
                    dr[k] = buf[k*NW + tid];
                    fr[k] = Ai[j0+k];
                }
                #pragma unroll
                for (int k = 0; k < BLK; ++k) {
                    S = dr[k]*S + fr[k];
                    fr[k] = S;
                }
                #pragma unroll
                for (int k = 0; k < BLK; ++k) Ai[j0+k] = fr[k];
            }
            __syncthreads();
        }
    }

    // ---- Phase B backward: recover f, A <- rowagg = S + T - 2f ----
    // Block NBLK-1's Dt tile resident in Ds1.
    {
        float T = 0.f, c = 0.f;
        for (int blk = NBLK-1; blk >= 0; --blk) {
            float* buf = (blk & 1) ? Ds1 : Ds0;
            bool more = (blk > 0);
            if (more) stage_async((blk & 1) ? Ds0 : Ds1, DtSrc + (blk-1)*STG, tid);
            cp_wait(more);
            __syncthreads();
            if (tid < NH) {
                int j0 = blk*BLK;
                float* Ai = A + tid*PAD;
                float dr[BLK], sr[BLK];
                #pragma unroll
                for (int k = 0; k < BLK; ++k) {
                    dr[k] = buf[k*NW + tid];
                    sr[k] = Ai[j0+k];                  // S values
                }
                float sprevb = (blk > 0) ? Ai[j0-1] : 0.f;  // prev block still holds S
                #pragma unroll
                for (int k = BLK-1; k >= 0; --k) {
                    float sp = (k > 0) ? sr[k-1] : sprevb;
                    float dj = (j0 + k > 0) ? dr[k] : 0.f;
                    float f  = sr[k] - dj*sp;
                    T = f + c*T;
                    Ai[j0+k] = sr[k] + T - 2.f*f;
                    c = dj;
                }
            }
            __syncthreads();
        }
    }

    // ---- Phase C: combine ----
    {
        const float4* Zi4 = (const float4*)(g_Zinv + dbase);
        const float4* cg4 = (const float4*)(g_colagg + base);
        float4* out4      = (float4*)(fout + base);
        #pragma unroll
        for (int r = 0; r < HW/4/256; ++r) {
            int v = tid + r*256;
            int idx = v * 4;
            int i = idx / NW;
            int j = idx - i*NW;
            float4 cgv = cg4[v];
            float4 zv  = Zi4[v];
            const float* Ap = A + i*PAD + j;
            float4 o;
            o.x = (cgv.x + Ap[0]) * zv.x;
            o.y = (cgv.y + Ap[1]) * zv.y;
            o.z = (cgv.z + Ap[2]) * zv.z;
            o.w = (cgv.w + Ap[3]) * zv.w;
            out4[v] = o;
        }
    }
}

// ---------------------------------------------------------------------------
extern "C" void kernel_launch(void* const* d_in, const int* in_sizes, int n_in,
                              void* d_out, int out_size) {
    const float* mask = (const float*)d_in[0];   // (4,19,192,192) fp32
    const float* edge = (const float*)d_in[1];   // (4,1,192,192)  fp32
    float* out = (float*)d_out;

    cudaFuncSetAttribute(iter_kernel,
                         cudaFuncAttributeMaxDynamicSharedMemorySize, SMEM_BYTES);

    dim3 g0(6, 6, NB), b0(32, 8);
    pk0_kernel<<<g0, b0>>>(edge);
    pkZc_kernel<<<(NB*NW*32 + 255)/256, 256>>>();
    pkZr_kernel<<<(NB*NH*32 + 255)/256, 256>>>();

    iter_kernel<<<NB*NC, 256, SMEM_BYTES>>>(mask, out);  // iter 1
    iter_kernel<<<NB*NC, 256, SMEM_BYTES>>>(out,  out);  // iter 2 (in-place safe)
    iter_kernel<<<NB*NC, 256, SMEM_BYTES>>>(out,  out);  // iter 3
}

// round 16
// speedup vs baseline: 5.4125x; 1.1108x over previous
#include <cuda_runtime.h>
#include <cstdint>

#define NB 4
#define NC 19
#define NH 192
#define NW 192
#define HW (NH*NW)
#define THETA 40.0f

// device scratch (no runtime allocation allowed)
__device__ float g_D     [NB*HW];       // D[b][i][j]
__device__ float g_Dt    [NB*HW];       // Dt[b][j][i]
__device__ float g_Zc    [NB*HW];
__device__ float g_Zinv  [NB*HW];
__device__ float g_featT [NB*NC*HW];    // transposed feat [b][c][j][i]
__device__ float g_rowagg[NB*NC*HW];    // rowagg [b][c][i][j]
__device__ float g_colT  [NB*NC*HW];    // colagg transposed [b][c][j][i]

// ---------------------------------------------------------------------------
// PK0: decays + tiled transpose (both D and Dt written coalesced)
__global__ void pk0_kernel(const float* __restrict__ edge) {
    __shared__ float t[32][33];
    int b  = blockIdx.z;
    int i0 = blockIdx.y * 32;
    int j0 = blockIdx.x * 32;
    int tx = threadIdx.x, ty = threadIdx.y;
    #pragma unroll
    for (int r = ty; r < 32; r += 8) {
        float e = edge[b*HW + (i0+r)*NW + j0 + tx];
        float d = __expf(-THETA * fmaxf(e, 0.f));
        g_D[b*HW + (i0+r)*NW + j0 + tx] = d;
        t[r][tx] = d;
    }
    __syncthreads();
    #pragma unroll
    for (int r = ty; r < 32; r += 8) {
        g_Dt[b*HW + (j0+r)*NW + i0 + tx] = t[tx][r];
    }
}

// ---------------------------------------------------------------------------
// pkZc: one warp per (b,j) column line; decays Dt row (contiguous).
// Zc[b][i][j] = S_i + T_i - 1 (ones-scan).
__global__ void pkZc_kernel() {
    int gw = (blockIdx.x * blockDim.x + threadIdx.x) >> 5;
    if (gw >= NB*NW) return;
    int lane = threadIdx.x & 31;
    int b = gw / NW, j = gw - b*NW;
    const float* dt = g_Dt + b*HW + j*NW;

    float dd[6];
    #pragma unroll
    for (int e = 0; e < 6; ++e) dd[e] = dt[lane*6 + e];
    float a = 1.f, s = 0.f;
    #pragma unroll
    for (int e = 0; e < 6; ++e) { s = dd[e]*s + 1.f; a *= dd[e]; }
    #pragma unroll
    for (int off = 1; off < 32; off <<= 1) {
        float pa = __shfl_up_sync(0xffffffffu, a, off);
        float pb = __shfl_up_sync(0xffffffffu, s, off);
        if (lane >= off) { s = a*pb + s; a = a*pa; }
    }
    float pre = __shfl_up_sync(0xffffffffu, s, 1);
    if (lane == 0) pre = 0.f;
    float Sv[6]; float x = pre;
    #pragma unroll
    for (int e = 0; e < 6; ++e) { x = dd[e]*x + 1.f; Sv[e] = x; }

    float cc[6];
    #pragma unroll
    for (int e = 0; e < 6; ++e) {
        int r = lane*6 + e;
        cc[e] = (r == 0) ? 0.f : dt[192 - r];
    }
    float ab = 1.f, sb = 0.f;
    #pragma unroll
    for (int e = 0; e < 6; ++e) { sb = cc[e]*sb + 1.f; ab *= cc[e]; }
    #pragma unroll
    for (int off = 1; off < 32; off <<= 1) {
        float pa = __shfl_up_sync(0xffffffffu, ab, off);
        float pb = __shfl_up_sync(0xffffffffu, sb, off);
        if (lane >= off) { sb = ab*pb + sb; ab = ab*pa; }
    }
    float preb = __shfl_up_sync(0xffffffffu, sb, 1);
    if (lane == 0) preb = 0.f;
    float Tv[6]; x = preb;
    #pragma unroll
    for (int e = 0; e < 6; ++e) { x = cc[e]*x + 1.f; Tv[e] = x; }

    float* zc = g_Zc + b*HW + j;
    #pragma unroll
    for (int e = 0; e < 6; ++e) {
        float Ti = __shfl_sync(0xffffffffu, Tv[5-e], 31 - lane);
        zc[(lane*6 + e)*NW] = Sv[e] + Ti - 1.f;
    }
}

// pkZr: one warp per (b,i) row line; Zinv = 1/(Zc + Zr), Zr = S + T - 2.
__global__ void pkZr_kernel() {
    int gw = (blockIdx.x * blockDim.x + threadIdx.x) >> 5;
    if (gw >= NB*NH) return;
    int lane = threadIdx.x & 31;
    int b = gw / NH, i = gw - b*NH;
    const float* dr = g_D + b*HW + i*NW;

    float dd[6];
    #pragma unroll
    for (int e = 0; e < 6; ++e) dd[e] = dr[lane*6 + e];
    float a = 1.f, s = 0.f;
    #pragma unroll
    for (int e = 0; e < 6; ++e) { s = dd[e]*s + 1.f; a *= dd[e]; }
    #pragma unroll
    for (int off = 1; off < 32; off <<= 1) {
        float pa = __shfl_up_sync(0xffffffffu, a, off);
        float pb = __shfl_up_sync(0xffffffffu, s, off);
        if (lane >= off) { s = a*pb + s; a = a*pa; }
    }
    float pre = __shfl_up_sync(0xffffffffu, s, 1);
    if (lane == 0) pre = 0.f;
    float Sv[6]; float x = pre;
    #pragma unroll
    for (int e = 0; e < 6; ++e) { x = dd[e]*x + 1.f; Sv[e] = x; }

    float cc[6];
    #pragma unroll
    for (int e = 0; e < 6; ++e) {
        int r = lane*6 + e;
        cc[e] = (r == 0) ? 0.f : dr[192 - r];
    }
    float ab = 1.f, sb = 0.f;
    #pragma unroll
    for (int e = 0; e < 6; ++e) { sb = cc[e]*sb + 1.f; ab *= cc[e]; }
    #pragma unroll
    for (int off = 1; off < 32; off <<= 1) {
        float pa = __shfl_up_sync(0xffffffffu, ab, off);
        float pb = __shfl_up_sync(0xffffffffu, sb, off);
        if (lane >= off) { sb = ab*pb + sb; ab = ab*pa; }
    }
    float preb = __shfl_up_sync(0xffffffffu, sb, 1);
    if (lane == 0) preb = 0.f;
    float Tv[6]; x = preb;
    #pragma unroll
    for (int e = 0; e < 6; ++e) { x = cc[e]*x + 1.f; Tv[e] = x; }

    const float* zc = g_Zc  + b*HW + i*NW;
    float*      zi = g_Zinv + b*HW + i*NW;
    #pragma unroll
    for (int e = 0; e < 6; ++e) {
        float Ti = __shfl_sync(0xffffffffu, Tv[5-e], 31 - lane);
        int jj = lane*6 + e;
        zi[jj] = 1.f / (zc[jj] + Sv[e] + Ti - 2.f);
    }
}

// ---------------------------------------------------------------------------
// t0: mask -> featT (tiled transpose per (b,c))
__global__ void t0_kernel(const float* __restrict__ mask) {
    __shared__ float t[32][33];
    int cta = blockIdx.x;            // bc*36 + tile
    int bc = cta / 36, tl = cta % 36;
    int ti = (tl / 6) * 32, tj = (tl % 6) * 32;
    int tx = threadIdx.x & 31, ty = threadIdx.x >> 5;
    #pragma unroll
    for (int rr = 0; rr < 4; ++rr) {
        int r = ty + rr*8;
        t[r][tx] = mask[bc*HW + (ti+r)*NW + tj + tx];
    }
    __syncthreads();
    #pragma unroll
    for (int rr = 0; rr < 4; ++rr) {
        int r = ty + rr*8;
        g_featT[bc*HW + (tj+r)*NW + ti + tx] = t[tx][r];
    }
}

// ---------------------------------------------------------------------------
// scanK: one warp per line; mode row (blk < HALF): feat lines + D,
// out rowagg = S+T-2f; mode col: featT lines + Dt, out colT = S+T-f.
// Lines staged through smem for coalesced global I/O.
#define SCAN_HALF (NB*NC*24)        // 8 lines per CTA, 24 groups per slice
__global__ void __launch_bounds__(256)
scanK_kernel(const float* __restrict__ feat) {
    __shared__ float sf[8*192];
    __shared__ float sd[8*192];
    int cta = blockIdx.x;
    bool colm = (cta >= SCAN_HALF);
    if (colm) cta -= SCAN_HALF;
    int bc  = cta / 24, grp = cta % 24;
    int b   = bc / NC;
    int tid = threadIdx.x;

    const float* src = (colm ? g_featT : feat) + bc*HW + grp*1536;
    const float* dsc = (colm ? g_Dt    : g_D ) + b *HW + grp*1536;
    float*       dst = (colm ? g_colT  : g_rowagg) + bc*HW + grp*1536;

    #pragma unroll
    for (int r = 0; r < 6; ++r) {
        int v = tid + r*256;
        sf[v] = src[v];
        sd[v] = dsc[v];
    }
    __syncthreads();

    int w = tid >> 5, lane = tid & 31;
    const float* f = sf + w*192;
    const float* d = sd + w*192;

    float dd[6], ff[6];
    #pragma unroll
    for (int e = 0; e < 6; ++e) { dd[e] = d[lane*6 + e]; ff[e] = f[lane*6 + e]; }

    // forward scan: S_i = d_i S_{i-1} + f_i
    float a = 1.f, s = 0.f;
    #pragma unroll
    for (int e = 0; e < 6; ++e) { s = dd[e]*s + ff[e]; a *= dd[e]; }
    #pragma unroll
    for (int off = 1; off < 32; off <<= 1) {
        float pa = __shfl_up_sync(0xffffffffu, a, off);
        float pb = __shfl_up_sync(0xffffffffu, s, off);
        if (lane >= off) { s = a*pb + s; a = a*pa; }
    }
    float pre = __shfl_up_sync(0xffffffffu, s, 1);
    if (lane == 0) pre = 0.f;
    float Sv[6]; float x = pre;
    #pragma unroll
    for (int e = 0; e < 6; ++e) { x = dd[e]*x + ff[e]; Sv[e] = x; }

    // backward scan: T_i = f_i + d_{i+1} T_{i+1}; reversed r: c'_r=d[192-r], b'_r=f[191-r]
    float cc[6], bb[6];
    #pragma unroll
    for (int e = 0; e < 6; ++e) {
        int r = lane*6 + e;
        cc[e] = (r == 0) ? 0.f : d[192 - r];
        bb[e] = f[191 - r];
    }
    float ab = 1.f, sb = 0.f;
    #pragma unroll
    for (int e = 0; e < 6; ++e) { sb = cc[e]*sb + bb[e]; ab *= cc[e]; }
    #pragma unroll
    for (int off = 1; off < 32; off <<= 1) {
        float pa = __shfl_up_sync(0xffffffffu, ab, off);
        float pb = __shfl_up_sync(0xffffffffu, sb, off);
        if (lane >= off) { sb = ab*pb + sb; ab = ab*pa; }
    }
    float preb = __shfl_up_sync(0xffffffffu, sb, 1);
    if (lane == 0) preb = 0.f;
    float Tv[6]; x = preb;
    #pragma unroll
    for (int e = 0; e < 6; ++e) { x = cc[e]*x + bb[e]; Tv[e] = x; }

    float fk = colm ? 1.f : 2.f;
    float* o = sf + w*192;              // reuse sf for output
    #pragma unroll
    for (int e = 0; e < 6; ++e) {
        float Ti = __shfl_sync(0xffffffffu, Tv[5-e], 31 - lane);
        o[lane*6 + e] = Sv[e] + Ti - fk*ff[e];
    }
    __syncthreads();
    #pragma unroll
    for (int r = 0; r < 6; ++r) {
        int v = tid + r*256;
        dst[v] = sf[v];
    }
}

// ---------------------------------------------------------------------------
// combK: out = (rowagg + colT^T) * Zinv; writes feat AND featT.
__global__ void __launch_bounds__(256)
combK_kernel(float* __restrict__ feat) {
    __shared__ float ct[32][33];
    __shared__ float ot[32][33];
    int cta = blockIdx.x;
    int bc = cta / 36, tl = cta % 36;
    int ti = (tl / 6) * 32, tj = (tl % 6) * 32;
    int b = bc / NC;
    int tx = threadIdx.x & 31, ty = threadIdx.x >> 5;

    // load colT tile: ct[jloc][iloc]
    #pragma unroll
    for (int rr = 0; rr < 4; ++rr) {
        int r = ty + rr*8;
        ct[r][tx] = g_colT[bc*HW + (tj+r)*NW + ti + tx];
    }
    __syncthreads();

    #pragma unroll
    for (int rr = 0; rr < 4; ++rr) {
        int r = ty + rr*8;
        int i = ti + r, j = tj + tx;
        int idx = bc*HW + i*NW + j;
        float v = (g_rowagg[idx] + ct[tx][r]) * g_Zinv[b*HW + i*NW + j];
        feat[idx] = v;
        ot[r][tx] = v;
    }
    __syncthreads();

    #pragma unroll
    for (int rr = 0; rr < 4; ++rr) {
        int r = ty + rr*8;
        g_featT[bc*HW + (tj+r)*NW + ti + tx] = ot[tx][r];
    }
}

// ---------------------------------------------------------------------------
extern "C" void kernel_launch(void* const* d_in, const int* in_sizes, int n_in,
                              void* d_out, int out_size) {
    const float* mask = (const float*)d_in[0];   // (4,19,192,192) fp32
    const float* edge = (const float*)d_in[1];   // (4,1,192,192)  fp32
    float* out = (float*)d_out;

    dim3 g0(6, 6, NB), b0(32, 8);
    pk0_kernel<<<g0, b0>>>(edge);
    pkZc_kernel<<<(NB*NW*32 + 255)/256, 256>>>();
    pkZr_kernel<<<(NB*NH*32 + 255)/256, 256>>>();
    t0_kernel<<<NB*NC*36, 256>>>(mask);

    // iter 1 (feat = mask)
    scanK_kernel<<<2*SCAN_HALF, 256>>>(mask);
    combK_kernel<<<NB*NC*36, 256>>>(out);
    // iter 2
    scanK_kernel<<<2*SCAN_HALF, 256>>>(out);
    combK_kernel<<<NB*NC*36, 256>>>(out);
    // iter 3
    scanK_kernel<<<2*SCAN_HALF, 256>>>(out);
    combK_kernel<<<NB*NC*36, 256>>>(out);
}